// round 6
// baseline (speedup 1.0000x reference)
#include <cuda_runtime.h>
#include <math.h>

// Problem constants (fixed per reference setup_inputs)
#define B_   8
#define C_   128
#define N_   4096
#define TINV 10.0f        // 1/TEMP
#define EPSN 1e-12f

#define TM 128            // rows per block tile
#define TN 128            // cols per block tile
#define PITCH 132         // smem pitch (multiple of 4 for float4 alignment)

// Scratch: normalized features, [b][n][c] layout (16 MB)
__device__ float g_vt[(size_t)B_ * N_ * C_];

// ---------------------------------------------------------------------------
// Kernel 0: zero the output scalar (harness poisons d_out)
// ---------------------------------------------------------------------------
__global__ void zero_out_kernel(float* out) { out[0] = 0.0f; }

// ---------------------------------------------------------------------------
// Kernel 1: normalize + transpose.
// features [B][C][N] -> g_vt [B][N][C], each point L2-normalized over C.
// One block handles 32 points of one batch. 256 threads.
// ---------------------------------------------------------------------------
__global__ void normalize_kernel(const float* __restrict__ feat) {
    __shared__ float t[C_][33];     // padded to kill bank conflicts
    __shared__ float invn[32];
    const int b   = blockIdx.y;
    const int n0  = blockIdx.x * 32;
    const int tid = threadIdx.x;

    const float* fb = feat + (size_t)b * C_ * N_;

    // Load [C=128][32] tile, coalesced along n
    for (int idx = tid; idx < C_ * 32; idx += 256) {
        int c = idx >> 5, nl = idx & 31;
        t[c][nl] = fb[(size_t)c * N_ + n0 + nl];
    }
    __syncthreads();

    // Each of 8 warps computes norms for 4 points
    const int w = tid >> 5, lane = tid & 31;
    #pragma unroll
    for (int p = 0; p < 4; p++) {
        int nl = w * 4 + p;
        float v0 = t[lane     ][nl];
        float v1 = t[lane + 32][nl];
        float v2 = t[lane + 64][nl];
        float v3 = t[lane + 96][nl];
        float s = v0 * v0 + v1 * v1 + v2 * v2 + v3 * v3;
        #pragma unroll
        for (int o = 16; o > 0; o >>= 1) s += __shfl_xor_sync(0xffffffffu, s, o);
        if (lane == 0) invn[nl] = 1.0f / fmaxf(sqrtf(s), EPSN);
    }
    __syncthreads();

    // Write normalized, transposed: vt[b][n][c] (coalesced along c)
    float* vb = g_vt + ((size_t)b * N_ + n0) * C_;
    for (int idx = tid; idx < 32 * C_; idx += 256) {
        int nl = idx >> 7, c = idx & 127;
        vb[(size_t)nl * C_ + c] = t[c][nl] * invn[nl];
    }
}

// ---------------------------------------------------------------------------
// Kernel 2: fused S = exp(V.V^T * 10), masked row-reductions, log, and
// global mean accumulation. Block = 128 rows of one batch; loops over all
// 4096 columns in 128-wide tiles. 256 threads, 8x8 micro-tile each.
// Dynamic smem: As[128k][132] + Bs[128k][132]  (~132 KB)
// ---------------------------------------------------------------------------
extern __shared__ float smem[];

__global__ void __launch_bounds__(256, 1)
loss_kernel(const int* __restrict__ labels, float* __restrict__ out) {
    float* As = smem;                    // [k][row], pitch 132
    float* Bs = smem + 128 * PITCH;      // [k][col], pitch 132
    __shared__ int lrow[TM];
    __shared__ int lcolS[TN];
    __shared__ float wsum[8];

    const int b     = blockIdx.y;
    const int rbase = blockIdx.x * TM;
    const int tid   = threadIdx.x;
    const int tx    = tid & 15;
    const int ty    = tid >> 4;

    const float* vb = g_vt + (size_t)b * N_ * C_;
    const int*   lb = labels + b * N_;

    // Load A tile: rows [rbase, rbase+128), all K; store transposed As[k][r]
    for (int idx = tid; idx < TM * C_; idx += 256) {
        int r = idx >> 7, c = idx & 127;
        As[c * PITCH + r] = vb[(size_t)(rbase + r) * C_ + c];
    }
    if (tid < TM) lrow[tid] = lb[rbase + tid];
    __syncthreads();

    int   myrow[8], mylab[8];
    float post[8], tott[8];
    #pragma unroll
    for (int i = 0; i < 8; i++) {
        myrow[i] = rbase + ty * 8 + i;
        mylab[i] = lrow[ty * 8 + i];
        post[i] = 0.0f;
        tott[i] = 0.0f;
    }

    for (int ct = 0; ct < N_ / TN; ct++) {
        const int cbase = ct * TN;
        __syncthreads();   // all threads done reading previous Bs
        for (int idx = tid; idx < TN * C_; idx += 256) {
            int r = idx >> 7, c = idx & 127;
            Bs[c * PITCH + r] = vb[(size_t)(cbase + r) * C_ + c];
        }
        if (tid < TN) lcolS[tid] = lb[cbase + tid];
        __syncthreads();

        float acc[8][8];
        #pragma unroll
        for (int i = 0; i < 8; i++)
            #pragma unroll
            for (int j = 0; j < 8; j++) acc[i][j] = 0.0f;

        #pragma unroll 4
        for (int k = 0; k < C_; k++) {
            float4 a0 = *(const float4*)(As + k * PITCH + ty * 8);
            float4 a1 = *(const float4*)(As + k * PITCH + ty * 8 + 4);
            float4 b0 = *(const float4*)(Bs + k * PITCH + tx * 8);
            float4 b1 = *(const float4*)(Bs + k * PITCH + tx * 8 + 4);
            float av[8] = {a0.x, a0.y, a0.z, a0.w, a1.x, a1.y, a1.z, a1.w};
            float bv[8] = {b0.x, b0.y, b0.z, b0.w, b1.x, b1.y, b1.z, b1.w};
            #pragma unroll
            for (int i = 0; i < 8; i++)
                #pragma unroll
                for (int j = 0; j < 8; j++)
                    acc[i][j] = fmaf(av[i], bv[j], acc[i][j]);
        }

        // Fused epilogue: exp, diagonal removal, label masking
        int gcol[8], clab[8];
        #pragma unroll
        for (int j = 0; j < 8; j++) {
            gcol[j] = cbase + tx * 8 + j;
            clab[j] = lcolS[tx * 8 + j];
        }
        #pragma unroll
        for (int i = 0; i < 8; i++) {
            float p = 0.0f, t2 = 0.0f;
            #pragma unroll
            for (int j = 0; j < 8; j++) {
                float e = __expf(acc[i][j] * TINV);
                e = (myrow[i] == gcol[j]) ? 0.0f : e;   // remove diagonal
                t2 += e;
                p += (mylab[i] == clab[j]) ? e : 0.0f;  // positives
            }
            post[i] += p;
            tott[i] += t2;
        }
    }

    // Cross-thread reduction: each row's partials live in 16 tx-threads.
    __syncthreads();                    // done with As/Bs; reuse for reduction
    float* redp = smem;                 // [128][16]
    float* redt = smem + TM * 16;       // [128][16]
    #pragma unroll
    for (int i = 0; i < 8; i++) {
        redp[(ty * 8 + i) * 16 + tx] = post[i];
        redt[(ty * 8 + i) * 16 + tx] = tott[i];
    }
    __syncthreads();

    float dev = 0.0f;
    if (tid < TM) {
        float p = 0.0f, t2 = 0.0f;
        #pragma unroll
        for (int j = 0; j < 16; j++) {
            p  += redp[tid * 16 + j];
            t2 += redt[tid * 16 + j];
        }
        dev = __logf(t2) - __logf(p);   // -log(pos/(pos+neg))
    }

    // Block-reduce dev and accumulate scaled mean into out
    #pragma unroll
    for (int o = 16; o > 0; o >>= 1) dev += __shfl_xor_sync(0xffffffffu, dev, o);
    if ((tid & 31) == 0) wsum[tid >> 5] = dev;
    __syncthreads();
    if (tid == 0) {
        float s = 0.0f;
        #pragma unroll
        for (int w = 0; w < 8; w++) s += wsum[w];
        atomicAdd(out, s * (1.0f / ((float)B_ * (float)N_)));
    }
}

// ---------------------------------------------------------------------------
// Launch
// ---------------------------------------------------------------------------
extern "C" void kernel_launch(void* const* d_in, const int* in_sizes, int n_in,
                              void* d_out, int out_size) {
    const float* feat   = (const float*)d_in[0];
    const int*   labels = (const int*)d_in[1];
    float*       out    = (float*)d_out;

    zero_out_kernel<<<1, 1>>>(out);

    dim3 gn(N_ / 32, B_);
    normalize_kernel<<<gn, 256>>>(feat);

    const size_t smem_bytes = (size_t)2 * 128 * PITCH * sizeof(float); // 135168
    cudaFuncSetAttribute(loss_kernel,
                         cudaFuncAttributeMaxDynamicSharedMemorySize,
                         (int)smem_bytes);
    dim3 gl(N_ / TM, B_);
    loss_kernel<<<gl, 256, smem_bytes>>>(labels, out);
}

// round 7
// speedup vs baseline: 1.0017x; 1.0017x over previous
#include <cuda_runtime.h>
#include <math.h>

// Problem constants (fixed per reference setup_inputs)
#define B_   8
#define C_   128
#define N_   4096
#define TINV 10.0f        // 1/TEMP
#define EPSN 1e-12f

#define TM 128            // rows per block tile
#define TN 128            // cols per block tile
#define PITCH 132         // smem pitch (multiple of 4 for float4 alignment)

// Scratch: normalized features, [b][n][c] layout (16 MB)
__device__ float g_vt[(size_t)B_ * N_ * C_];

// ---------------------------------------------------------------------------
// Kernel 0: zero the output scalar (harness poisons d_out)
// ---------------------------------------------------------------------------
__global__ void zero_out_kernel(float* out) { out[0] = 0.0f; }

// ---------------------------------------------------------------------------
// Kernel 1: normalize + transpose.
// features [B][C][N] -> g_vt [B][N][C], each point L2-normalized over C.
// One block handles 32 points of one batch. 256 threads.
// ---------------------------------------------------------------------------
__global__ void normalize_kernel(const float* __restrict__ feat) {
    __shared__ float t[C_][33];     // padded to kill bank conflicts
    __shared__ float invn[32];
    const int b   = blockIdx.y;
    const int n0  = blockIdx.x * 32;
    const int tid = threadIdx.x;

    const float* fb = feat + (size_t)b * C_ * N_;

    // Load [C=128][32] tile, coalesced along n
    for (int idx = tid; idx < C_ * 32; idx += 256) {
        int c = idx >> 5, nl = idx & 31;
        t[c][nl] = fb[(size_t)c * N_ + n0 + nl];
    }
    __syncthreads();

    // Each of 8 warps computes norms for 4 points
    const int w = tid >> 5, lane = tid & 31;
    #pragma unroll
    for (int p = 0; p < 4; p++) {
        int nl = w * 4 + p;
        float v0 = t[lane     ][nl];
        float v1 = t[lane + 32][nl];
        float v2 = t[lane + 64][nl];
        float v3 = t[lane + 96][nl];
        float s = v0 * v0 + v1 * v1 + v2 * v2 + v3 * v3;
        #pragma unroll
        for (int o = 16; o > 0; o >>= 1) s += __shfl_xor_sync(0xffffffffu, s, o);
        if (lane == 0) invn[nl] = 1.0f / fmaxf(sqrtf(s), EPSN);
    }
    __syncthreads();

    // Write normalized, transposed: vt[b][n][c] (coalesced along c)
    float* vb = g_vt + ((size_t)b * N_ + n0) * C_;
    for (int idx = tid; idx < 32 * C_; idx += 256) {
        int nl = idx >> 7, c = idx & 127;
        vb[(size_t)nl * C_ + c] = t[c][nl] * invn[nl];
    }
}

// ---------------------------------------------------------------------------
// Kernel 2: fused S = exp(V.V^T * 10), masked row-reductions, log, and
// global mean accumulation. Block = 128 rows of one batch; loops over all
// 4096 columns in 128-wide tiles. 256 threads, 8x8 micro-tile each.
// Dynamic smem: As[128k][132] + Bs[128k][132]  (~132 KB)
// ---------------------------------------------------------------------------
extern __shared__ float smem[];

__global__ void __launch_bounds__(256, 1)
loss_kernel(const int* __restrict__ labels, float* __restrict__ out) {
    float* As = smem;                    // [k][row], pitch 132
    float* Bs = smem + 128 * PITCH;      // [k][col], pitch 132
    __shared__ int lrow[TM];
    __shared__ int lcolS[TN];
    __shared__ float wsum[8];

    const int b     = blockIdx.y;
    const int rbase = blockIdx.x * TM;
    const int tid   = threadIdx.x;
    const int tx    = tid & 15;
    const int ty    = tid >> 4;

    const float* vb = g_vt + (size_t)b * N_ * C_;
    const int*   lb = labels + b * N_;

    // Load A tile: rows [rbase, rbase+128), all K; store transposed As[k][r]
    for (int idx = tid; idx < TM * C_; idx += 256) {
        int r = idx >> 7, c = idx & 127;
        As[c * PITCH + r] = vb[(size_t)(rbase + r) * C_ + c];
    }
    if (tid < TM) lrow[tid] = lb[rbase + tid];
    __syncthreads();

    int   myrow[8], mylab[8];
    float post[8], tott[8];
    #pragma unroll
    for (int i = 0; i < 8; i++) {
        myrow[i] = rbase + ty * 8 + i;
        mylab[i] = lrow[ty * 8 + i];
        post[i] = 0.0f;
        tott[i] = 0.0f;
    }

    for (int ct = 0; ct < N_ / TN; ct++) {
        const int cbase = ct * TN;
        __syncthreads();   // all threads done reading previous Bs
        for (int idx = tid; idx < TN * C_; idx += 256) {
            int r = idx >> 7, c = idx & 127;
            Bs[c * PITCH + r] = vb[(size_t)(cbase + r) * C_ + c];
        }
        if (tid < TN) lcolS[tid] = lb[cbase + tid];
        __syncthreads();

        float acc[8][8];
        #pragma unroll
        for (int i = 0; i < 8; i++)
            #pragma unroll
            for (int j = 0; j < 8; j++) acc[i][j] = 0.0f;

        #pragma unroll 4
        for (int k = 0; k < C_; k++) {
            float4 a0 = *(const float4*)(As + k * PITCH + ty * 8);
            float4 a1 = *(const float4*)(As + k * PITCH + ty * 8 + 4);
            float4 b0 = *(const float4*)(Bs + k * PITCH + tx * 8);
            float4 b1 = *(const float4*)(Bs + k * PITCH + tx * 8 + 4);
            float av[8] = {a0.x, a0.y, a0.z, a0.w, a1.x, a1.y, a1.z, a1.w};
            float bv[8] = {b0.x, b0.y, b0.z, b0.w, b1.x, b1.y, b1.z, b1.w};
            #pragma unroll
            for (int i = 0; i < 8; i++)
                #pragma unroll
                for (int j = 0; j < 8; j++)
                    acc[i][j] = fmaf(av[i], bv[j], acc[i][j]);
        }

        // Fused epilogue: exp, diagonal removal, label masking
        int gcol[8], clab[8];
        #pragma unroll
        for (int j = 0; j < 8; j++) {
            gcol[j] = cbase + tx * 8 + j;
            clab[j] = lcolS[tx * 8 + j];
        }
        #pragma unroll
        for (int i = 0; i < 8; i++) {
            float p = 0.0f, t2 = 0.0f;
            #pragma unroll
            for (int j = 0; j < 8; j++) {
                float e = __expf(acc[i][j] * TINV);
                e = (myrow[i] == gcol[j]) ? 0.0f : e;   // remove diagonal
                t2 += e;
                p += (mylab[i] == clab[j]) ? e : 0.0f;  // positives
            }
            post[i] += p;
            tott[i] += t2;
        }
    }

    // Cross-thread reduction: each row's partials live in 16 tx-threads.
    __syncthreads();                    // done with As/Bs; reuse for reduction
    float* redp = smem;                 // [128][16]
    float* redt = smem + TM * 16;       // [128][16]
    #pragma unroll
    for (int i = 0; i < 8; i++) {
        redp[(ty * 8 + i) * 16 + tx] = post[i];
        redt[(ty * 8 + i) * 16 + tx] = tott[i];
    }
    __syncthreads();

    float dev = 0.0f;
    if (tid < TM) {
        float p = 0.0f, t2 = 0.0f;
        #pragma unroll
        for (int j = 0; j < 16; j++) {
            p  += redp[tid * 16 + j];
            t2 += redt[tid * 16 + j];
        }
        dev = __logf(t2) - __logf(p);   // -log(pos/(pos+neg))
    }

    // Block-reduce dev and accumulate scaled mean into out
    #pragma unroll
    for (int o = 16; o > 0; o >>= 1) dev += __shfl_xor_sync(0xffffffffu, dev, o);
    if ((tid & 31) == 0) wsum[tid >> 5] = dev;
    __syncthreads();
    if (tid == 0) {
        float s = 0.0f;
        #pragma unroll
        for (int w = 0; w < 8; w++) s += wsum[w];
        atomicAdd(out, s * (1.0f / ((float)B_ * (float)N_)));
    }
}

// ---------------------------------------------------------------------------
// Launch
// ---------------------------------------------------------------------------
extern "C" void kernel_launch(void* const* d_in, const int* in_sizes, int n_in,
                              void* d_out, int out_size) {
    const float* feat   = (const float*)d_in[0];
    const int*   labels = (const int*)d_in[1];
    float*       out    = (float*)d_out;

    zero_out_kernel<<<1, 1>>>(out);

    dim3 gn(N_ / 32, B_);
    normalize_kernel<<<gn, 256>>>(feat);

    const size_t smem_bytes = (size_t)2 * 128 * PITCH * sizeof(float); // 135168
    cudaFuncSetAttribute(loss_kernel,
                         cudaFuncAttributeMaxDynamicSharedMemorySize,
                         (int)smem_bytes);
    dim3 gl(N_ / TM, B_);
    loss_kernel<<<gl, 256, smem_bytes>>>(labels, out);
}

// round 9
// speedup vs baseline: 6.3897x; 6.3789x over previous
#include <cuda_runtime.h>
#include <cuda_fp16.h>
#include <math.h>
#include <stdint.h>

// ---------------------------------------------------------------------------
// Problem constants
// ---------------------------------------------------------------------------
#define B_   8
#define C_   128
#define N_   4096
#define EPSN 1e-12f
// exp(x/0.1) = 2^(x * 10*log2(e)); fold sqrt of scale into both vectors.
#define ALPHA 3.7982826f          // sqrt(14.4269504089)

#define TM   128                  // CTA rows
#define TN   128                  // cols per iteration tile
#define NITER (N_ / TN)           // 32

// Scratch: normalized+scaled features fp16, [b][n][c] (8 MB)
__device__ __align__(16) __half g_vh[(size_t)B_ * N_ * C_];

// ---------------------------------------------------------------------------
// Helpers
// ---------------------------------------------------------------------------
__device__ __forceinline__ uint32_t smem_u32(const void* p) {
    uint32_t a;
    asm("{ .reg .u64 t; cvta.to.shared.u64 t, %1; cvt.u32.u64 %0, t; }"
        : "=r"(a) : "l"(p));
    return a;
}

__device__ __forceinline__ float ex2f(float x) {
    float y;
    asm("ex2.approx.f32 %0, %1;" : "=f"(y) : "f"(x));
    return y;
}

#define LDSM4(R0, R1, R2, R3, ADDR) \
    asm volatile("ldmatrix.sync.aligned.m8n8.x4.shared.b16 {%0,%1,%2,%3}, [%4];" \
                 : "=r"(R0), "=r"(R1), "=r"(R2), "=r"(R3) : "r"(ADDR))

#define MMA16816(AC, A0, A1, A2, A3, Bv0, Bv1) \
    asm volatile("mma.sync.aligned.m16n8k16.row.col.f32.f16.f16.f32 " \
                 "{%0,%1,%2,%3}, {%4,%5,%6,%7}, {%8,%9}, {%0,%1,%2,%3};" \
                 : "+f"((AC)[0]), "+f"((AC)[1]), "+f"((AC)[2]), "+f"((AC)[3]) \
                 : "r"(A0), "r"(A1), "r"(A2), "r"(A3), "r"(Bv0), "r"(Bv1))

#define CP_ASYNC16(DST, SRC) \
    asm volatile("cp.async.cg.shared.global [%0], [%1], 16;" :: "r"(DST), "l"(SRC))
#define CP_COMMIT()  asm volatile("cp.async.commit_group;" ::: "memory")
#define CP_WAIT0()   asm volatile("cp.async.wait_group 0;" ::: "memory")

// ---------------------------------------------------------------------------
// Kernel 0: zero output scalar
// ---------------------------------------------------------------------------
__global__ void zero_out_kernel(float* out) { out[0] = 0.0f; }

// ---------------------------------------------------------------------------
// Kernel 1: normalize + scale by ALPHA + transpose -> fp16 [b][n][c]
// ---------------------------------------------------------------------------
__global__ void normalize_kernel(const float* __restrict__ feat) {
    __shared__ float t[C_][33];
    __shared__ float invn[32];
    const int b = blockIdx.y, n0 = blockIdx.x * 32, tid = threadIdx.x;
    const float* fb = feat + (size_t)b * C_ * N_;

    for (int idx = tid; idx < C_ * 32; idx += 256) {
        int c = idx >> 5, nl = idx & 31;
        t[c][nl] = fb[(size_t)c * N_ + n0 + nl];
    }
    __syncthreads();

    const int w = tid >> 5, lane = tid & 31;
    #pragma unroll
    for (int p = 0; p < 4; p++) {
        int nl = w * 4 + p;
        float v0 = t[lane][nl], v1 = t[lane + 32][nl];
        float v2 = t[lane + 64][nl], v3 = t[lane + 96][nl];
        float s = v0 * v0 + v1 * v1 + v2 * v2 + v3 * v3;
        #pragma unroll
        for (int o = 16; o > 0; o >>= 1) s += __shfl_xor_sync(0xffffffffu, s, o);
        if (lane == 0) invn[nl] = ALPHA / fmaxf(sqrtf(s), EPSN);
    }
    __syncthreads();

    __half* vb = g_vh + ((size_t)b * N_ + n0) * C_;
    for (int idx = tid; idx < 32 * C_; idx += 256) {
        int nl = idx >> 7, c = idx & 127;
        vb[(size_t)nl * C_ + c] = __float2half(t[c][nl] * invn[nl]);
    }
}

// ---------------------------------------------------------------------------
// Tile copy: 128 rows x 256B (128 fp16) global -> swizzled smem via cp.async.
// Swizzle: physical 16B-chunk = c ^ (row & 7)  (conflict-free ldmatrix + STS)
// ---------------------------------------------------------------------------
__device__ __forceinline__ void cp_tile(uint32_t sbase,
                                        const __half* __restrict__ src,
                                        int tid) {
    #pragma unroll
    for (int it = 0; it < 8; it++) {
        int idx = tid + it * 256;
        int r = idx >> 4, c = idx & 15;
        uint32_t dst = sbase + (uint32_t)r * 256u + (uint32_t)((c ^ (r & 7)) << 4);
        const char* g = (const char*)src + (size_t)r * 256 + c * 16;
        CP_ASYNC16(dst, g);
    }
}

// ---------------------------------------------------------------------------
// Kernel 2: HMMA GEMM + fused exp2/mask epilogue.
// Grid (32, 8), 256 threads. Warp layout 4(M) x 2(N); warp tile 32x64.
// Dyn smem: A 32K | B0 32K | B1 32K | cmask 8K | posS 1K | totS 1K = 106 KB
// ---------------------------------------------------------------------------
#define SM_B0    32768
#define SM_B1    65536
#define SM_CMASK 98304
#define SM_POSS  (98304 + 8192)
#define SM_TOTS  (SM_POSS + 1024)
#define SM_DYN   (SM_TOTS + 1024)

__global__ void __launch_bounds__(256, 1)
loss_kernel(const int* __restrict__ labels, float* __restrict__ out) {
    extern __shared__ char sm[];
    __shared__ float partial[8];

    const int tid = threadIdx.x, wid = tid >> 5, lane = tid & 31;
    const int b = blockIdx.y, r0 = blockIdx.x * TM;

    unsigned* cmask = (unsigned*)(sm + SM_CMASK);   // [16 classes][128 words]
    float* posS = (float*)(sm + SM_POSS);           // [128][2]
    float* totS = (float*)(sm + SM_TOTS);

    const int* lb = labels + b * N_;
    const __half* vb = g_vh + (size_t)b * N_ * C_;

    const uint32_t sA  = smem_u32(sm);
    const uint32_t sB0 = smem_u32(sm + SM_B0);
    const uint32_t sB1 = smem_u32(sm + SM_B1);

    // --- prologue: async copy A tile + B tile 0 ---
    cp_tile(sA,  vb + (size_t)r0 * C_, tid);
    cp_tile(sB0, vb, tid);
    CP_COMMIT();

    // --- build per-class column bitmasks for full batch (overlaps copies) ---
    {
        int labv[16];
        #pragma unroll
        for (int i = 0; i < 16; i++) labv[i] = lb[(wid * 16 + i) * 32 + lane];
        #pragma unroll
        for (int i = 0; i < 16; i++) {
            int k = wid * 16 + i;
            #pragma unroll
            for (int c = 0; c < 16; c++) {
                unsigned m = __ballot_sync(0xffffffffu, labv[i] == c);
                if (lane == c) cmask[c * 128 + k] = m;
            }
        }
    }

    const int warpM = (wid & 3) * 32;
    const int warpN = (wid >> 2) * 64;

    // Row identities for this thread's accumulator rows
    int growb[2];
    int labr[2][2];
    #pragma unroll
    for (int mt = 0; mt < 2; mt++) {
        growb[mt] = r0 + warpM + mt * 16 + (lane >> 2);
        labr[mt][0] = lb[growb[mt]];
        labr[mt][1] = lb[growb[mt] + 8];
    }

    // ldmatrix per-lane address components
    const int rA  = warpM + (lane & 15);       // A row (+ mt*16)
    const int csA = lane >> 4;                 // A k-chunk select
    const int rBl = (lane & 7) + ((lane & 16) >> 1);   // B row within n16
    const int csB = (lane >> 3) & 1;                   // B k-chunk select

    uint32_t bRow[4];
    int bR7[4];
    #pragma unroll
    for (int np = 0; np < 4; np++) {
        int row = warpN + np * 16 + rBl;
        bRow[np] = (uint32_t)row * 256u;
        bR7[np] = row & 7;
    }

    CP_WAIT0();
    __syncthreads();

    // --- load A fragments once, cached in registers for all 32 iterations ---
    uint32_t af[2][8][4];
    #pragma unroll
    for (int mt = 0; mt < 2; mt++) {
        int row = rA + mt * 16;
        uint32_t base = sA + (uint32_t)row * 256u;
        int r7 = row & 7;
        #pragma unroll
        for (int k = 0; k < 8; k++) {
            uint32_t addr = base + (uint32_t)(((2 * k + csA) ^ r7) << 4);
            LDSM4(af[mt][k][0], af[mt][k][1], af[mt][k][2], af[mt][k][3], addr);
        }
    }

    float pos[4] = {0.f, 0.f, 0.f, 0.f};
    float tot[4] = {0.f, 0.f, 0.f, 0.f};
    const int diagTile = blockIdx.x;

    for (int t = 0; t < NITER; t++) {
        const uint32_t sB = (t & 1) ? sB1 : sB0;
        if (t + 1 < NITER) {
            cp_tile(((t + 1) & 1) ? sB1 : sB0,
                    vb + (size_t)(t + 1) * TN * C_, tid);
            CP_COMMIT();
        }

        float acc[2][8][4];
        #pragma unroll
        for (int mt = 0; mt < 2; mt++)
            #pragma unroll
            for (int nt = 0; nt < 8; nt++)
                #pragma unroll
                for (int q = 0; q < 4; q++) acc[mt][nt][q] = 0.0f;

        #pragma unroll
        for (int k = 0; k < 8; k++) {
            uint32_t bf[4][4];
            #pragma unroll
            for (int np = 0; np < 4; np++) {
                uint32_t addr = sB + bRow[np]
                              + (uint32_t)(((2 * k + csB) ^ bR7[np]) << 4);
                LDSM4(bf[np][0], bf[np][1], bf[np][2], bf[np][3], addr);
            }
            #pragma unroll
            for (int mt = 0; mt < 2; mt++) {
                #pragma unroll
                for (int nt = 0; nt < 8; nt++) {
                    const int np = nt >> 1;
                    if (nt & 1) {
                        MMA16816(acc[mt][nt], af[mt][k][0], af[mt][k][1],
                                 af[mt][k][2], af[mt][k][3],
                                 bf[np][2], bf[np][3]);
                    } else {
                        MMA16816(acc[mt][nt], af[mt][k][0], af[mt][k][1],
                                 af[mt][k][2], af[mt][k][3],
                                 bf[np][0], bf[np][1]);
                    }
                }
            }
        }

        // --- fused epilogue: exp2, diagonal removal, label masking ---
        const int cb = t * TN;
        const bool isDiag = (t == diagTile);
        #pragma unroll
        for (int mt = 0; mt < 2; mt++) {
            const int mwb0 = labr[mt][0] * 128 + t * 4 + (warpN >> 5);
            const int mwb1 = labr[mt][1] * 128 + t * 4 + (warpN >> 5);
            const unsigned mw00 = cmask[mwb0],     mw01 = cmask[mwb0 + 1];
            const unsigned mw10 = cmask[mwb1],     mw11 = cmask[mwb1 + 1];
            const int grow0 = growb[mt], grow1 = growb[mt] + 8;
            float t0 = 0.f, t1 = 0.f, p0 = 0.f, p1 = 0.f;
            #pragma unroll
            for (int nt = 0; nt < 8; nt++) {
                const unsigned w0 = (nt < 4) ? mw00 : mw01;
                const unsigned w1 = (nt < 4) ? mw10 : mw11;
                const int sh = (nt & 3) * 8 + 2 * (lane & 3);
                const unsigned b0 = w0 >> sh;
                const unsigned b1 = w1 >> sh;
                float e00 = ex2f(acc[mt][nt][0]);
                float e01 = ex2f(acc[mt][nt][1]);
                float e10 = ex2f(acc[mt][nt][2]);
                float e11 = ex2f(acc[mt][nt][3]);
                if (isDiag) {
                    const int gc = cb + warpN + nt * 8 + 2 * (lane & 3);
                    if (grow0 == gc)     e00 = 0.f;
                    if (grow0 == gc + 1) e01 = 0.f;
                    if (grow1 == gc)     e10 = 0.f;
                    if (grow1 == gc + 1) e11 = 0.f;
                }
                t0 += e00 + e01;
                t1 += e10 + e11;
                p0 += ((b0 & 1u) ? e00 : 0.f) + ((b0 & 2u) ? e01 : 0.f);
                p1 += ((b1 & 1u) ? e10 : 0.f) + ((b1 & 2u) ? e11 : 0.f);
            }
            tot[mt * 2 + 0] += t0;  tot[mt * 2 + 1] += t1;
            pos[mt * 2 + 0] += p0;  pos[mt * 2 + 1] += p1;
        }

        if (t + 1 < NITER) CP_WAIT0();
        __syncthreads();
    }

    // --- reduce over the 4 lanes sharing each row, then across warp halves ---
    #pragma unroll
    for (int i = 0; i < 4; i++) {
        pos[i] += __shfl_xor_sync(0xffffffffu, pos[i], 1);
        pos[i] += __shfl_xor_sync(0xffffffffu, pos[i], 2);
        tot[i] += __shfl_xor_sync(0xffffffffu, tot[i], 1);
        tot[i] += __shfl_xor_sync(0xffffffffu, tot[i], 2);
    }
    const int widN = wid >> 2;
    if ((lane & 3) == 0) {
        #pragma unroll
        for (int mt = 0; mt < 2; mt++) {
            int rl = warpM + mt * 16 + (lane >> 2);
            posS[rl * 2 + widN]       = pos[mt * 2 + 0];
            totS[rl * 2 + widN]       = tot[mt * 2 + 0];
            posS[(rl + 8) * 2 + widN] = pos[mt * 2 + 1];
            totS[(rl + 8) * 2 + widN] = tot[mt * 2 + 1];
        }
    }
    __syncthreads();

    float dev = 0.0f;
    if (tid < TM) {
        float P = posS[tid * 2] + posS[tid * 2 + 1];
        float T = totS[tid * 2] + totS[tid * 2 + 1];
        dev = __logf(T) - __logf(P);      // -log(pos/(pos+neg))
    }
    #pragma unroll
    for (int o = 16; o > 0; o >>= 1) dev += __shfl_xor_sync(0xffffffffu, dev, o);
    if (lane == 0) partial[wid] = dev;
    __syncthreads();
    if (tid == 0) {
        float s = 0.0f;
        #pragma unroll
        for (int w = 0; w < 8; w++) s += partial[w];
        atomicAdd(out, s * (1.0f / ((float)B_ * (float)N_)));
    }
}

// ---------------------------------------------------------------------------
// Launch
// ---------------------------------------------------------------------------
extern "C" void kernel_launch(void* const* d_in, const int* in_sizes, int n_in,
                              void* d_out, int out_size) {
    const float* feat   = (const float*)d_in[0];
    const int*   labels = (const int*)d_in[1];
    float*       out    = (float*)d_out;

    zero_out_kernel<<<1, 1>>>(out);

    dim3 gn(N_ / 32, B_);
    normalize_kernel<<<gn, 256>>>(feat);

    cudaFuncSetAttribute(loss_kernel,
                         cudaFuncAttributeMaxDynamicSharedMemorySize, SM_DYN);
    dim3 gl(N_ / TM, B_);
    loss_kernel<<<gl, 256, SM_DYN>>>(labels, out);
}

// round 10
// speedup vs baseline: 7.3690x; 1.1533x over previous
#include <cuda_runtime.h>
#include <cuda_fp16.h>
#include <math.h>
#include <stdint.h>

// ---------------------------------------------------------------------------
// Problem constants
// ---------------------------------------------------------------------------
#define B_   8
#define C_   128
#define N_   4096
#define EPSN 1e-12f
// exp(x/0.1) = 2^(x * 10*log2(e)); fold sqrt of scale into both vectors.
#define ALPHA 3.7982826f          // sqrt(14.4269504089)

#define TM   128                  // rows per unit
#define TN   128                  // cols per iteration tile
#define IPU  8                    // iterations (col tiles) per unit
#define NU   (B_ * 32 * 4)        // 1024 work units (batch x row-tile x quarter)
#define GRIDP 148                 // persistent CTAs (1 per SM)

// Scratch: normalized+scaled features fp16, [b][n][c] (8 MB)
__device__ __align__(16) __half g_vh[(size_t)B_ * N_ * C_];
// Per-row partial sums (merged across col-quarter units)
__device__ float g_pos[B_ * N_];
__device__ float g_tot[B_ * N_];

// ---------------------------------------------------------------------------
// Helpers
// ---------------------------------------------------------------------------
__device__ __forceinline__ uint32_t smem_u32(const void* p) {
    uint32_t a;
    asm("{ .reg .u64 t; cvta.to.shared.u64 t, %1; cvt.u32.u64 %0, t; }"
        : "=r"(a) : "l"(p));
    return a;
}

__device__ __forceinline__ float ex2f(float x) {
    float y;
    asm("ex2.approx.f32 %0, %1;" : "=f"(y) : "f"(x));
    return y;
}

#define LDSM4(R0, R1, R2, R3, ADDR) \
    asm volatile("ldmatrix.sync.aligned.m8n8.x4.shared.b16 {%0,%1,%2,%3}, [%4];" \
                 : "=r"(R0), "=r"(R1), "=r"(R2), "=r"(R3) : "r"(ADDR))

#define MMA16816(AC, A0, A1, A2, A3, Bv0, Bv1) \
    asm volatile("mma.sync.aligned.m16n8k16.row.col.f32.f16.f16.f32 " \
                 "{%0,%1,%2,%3}, {%4,%5,%6,%7}, {%8,%9}, {%0,%1,%2,%3};" \
                 : "+f"((AC)[0]), "+f"((AC)[1]), "+f"((AC)[2]), "+f"((AC)[3]) \
                 : "r"(A0), "r"(A1), "r"(A2), "r"(A3), "r"(Bv0), "r"(Bv1))

#define CP_ASYNC16(DST, SRC) \
    asm volatile("cp.async.cg.shared.global [%0], [%1], 16;" :: "r"(DST), "l"(SRC))
#define CP_COMMIT()  asm volatile("cp.async.commit_group;" ::: "memory")
#define CP_WAIT0()   asm volatile("cp.async.wait_group 0;" ::: "memory")

// ---------------------------------------------------------------------------
// Kernel 0: zero output scalar + per-row accumulators
// ---------------------------------------------------------------------------
__global__ void zero_kernel(float* out) {
    int idx = blockIdx.x * blockDim.x + threadIdx.x;
    if (idx == 0) out[0] = 0.0f;
    for (int i = idx; i < B_ * N_; i += gridDim.x * blockDim.x) {
        g_pos[i] = 0.0f;
        g_tot[i] = 0.0f;
    }
}

// ---------------------------------------------------------------------------
// Kernel 1: normalize + scale by ALPHA + transpose -> fp16 [b][n][c]
// ---------------------------------------------------------------------------
__global__ void normalize_kernel(const float* __restrict__ feat) {
    __shared__ float t[C_][33];
    __shared__ float invn[32];
    const int b = blockIdx.y, n0 = blockIdx.x * 32, tid = threadIdx.x;
    const float* fb = feat + (size_t)b * C_ * N_;

    for (int idx = tid; idx < C_ * 32; idx += 256) {
        int c = idx >> 5, nl = idx & 31;
        t[c][nl] = fb[(size_t)c * N_ + n0 + nl];
    }
    __syncthreads();

    const int w = tid >> 5, lane = tid & 31;
    #pragma unroll
    for (int p = 0; p < 4; p++) {
        int nl = w * 4 + p;
        float v0 = t[lane][nl], v1 = t[lane + 32][nl];
        float v2 = t[lane + 64][nl], v3 = t[lane + 96][nl];
        float s = v0 * v0 + v1 * v1 + v2 * v2 + v3 * v3;
        #pragma unroll
        for (int o = 16; o > 0; o >>= 1) s += __shfl_xor_sync(0xffffffffu, s, o);
        if (lane == 0) invn[nl] = ALPHA / fmaxf(sqrtf(s), EPSN);
    }
    __syncthreads();

    __half* vb = g_vh + ((size_t)b * N_ + n0) * C_;
    for (int idx = tid; idx < 32 * C_; idx += 256) {
        int nl = idx >> 7, c = idx & 127;
        vb[(size_t)nl * C_ + c] = __float2half(t[c][nl] * invn[nl]);
    }
}

// ---------------------------------------------------------------------------
// Tile copy: 128 rows x 256B global -> swizzled smem via cp.async.
// Swizzle: physical 16B-chunk = c ^ (row & 7)
// ---------------------------------------------------------------------------
__device__ __forceinline__ void cp_tile(uint32_t sbase,
                                        const __half* __restrict__ src,
                                        int tid) {
    #pragma unroll
    for (int it = 0; it < 8; it++) {
        int idx = tid + it * 256;
        int r = idx >> 4, c = idx & 15;
        uint32_t dst = sbase + (uint32_t)r * 256u + (uint32_t)((c ^ (r & 7)) << 4);
        const char* g = (const char*)src + (size_t)r * 256 + c * 16;
        CP_ASYNC16(dst, g);
    }
}

// ---------------------------------------------------------------------------
// Half-tile K-loop: 32 rows x 32 cols x K=128 into acc (2 mt x 4 ntl x 4).
// ---------------------------------------------------------------------------
__device__ __forceinline__ void khalf(float (&acc)[2][4][4],
                                      const uint32_t (&af)[2][8][4],
                                      uint32_t sB,
                                      uint32_t bRow0, int bR70,
                                      uint32_t bRow1, int bR71, int csB) {
    #pragma unroll
    for (int mt = 0; mt < 2; mt++)
        #pragma unroll
        for (int nt = 0; nt < 4; nt++)
            #pragma unroll
            for (int q = 0; q < 4; q++) acc[mt][nt][q] = 0.0f;

    #pragma unroll
    for (int k = 0; k < 8; k++) {
        uint32_t bf0[4], bf1[4];
        LDSM4(bf0[0], bf0[1], bf0[2], bf0[3],
              sB + bRow0 + (uint32_t)(((2 * k + csB) ^ bR70) << 4));
        LDSM4(bf1[0], bf1[1], bf1[2], bf1[3],
              sB + bRow1 + (uint32_t)(((2 * k + csB) ^ bR71) << 4));
        #pragma unroll
        for (int mt = 0; mt < 2; mt++) {
            MMA16816(acc[mt][0], af[mt][k][0], af[mt][k][1], af[mt][k][2],
                     af[mt][k][3], bf0[0], bf0[1]);
            MMA16816(acc[mt][1], af[mt][k][0], af[mt][k][1], af[mt][k][2],
                     af[mt][k][3], bf0[2], bf0[3]);
            MMA16816(acc[mt][2], af[mt][k][0], af[mt][k][1], af[mt][k][2],
                     af[mt][k][3], bf1[0], bf1[1]);
            MMA16816(acc[mt][3], af[mt][k][0], af[mt][k][1], af[mt][k][2],
                     af[mt][k][3], bf1[2], bf1[3]);
        }
    }
}

// ---------------------------------------------------------------------------
// Epilogue of one half-tile: exp2, diagonal removal, label masking.
// ---------------------------------------------------------------------------
__device__ __forceinline__ void epi_half(const float (&acc)[2][4][4],
                                         int i, int h,
                                         const unsigned* __restrict__ cmask,
                                         const int (&labr)[2][2],
                                         const int (&growb)[2],
                                         int warpN, int lane, int rt, int cq,
                                         float (&pos)[4], float (&tot)[4]) {
    const int coff = warpN + h * 32;
    const int lw = i * 4 + (coff >> 5);          // mask word within quarter
    const int cb = cq * 1024 + i * 128 + coff;   // in-batch column base
    const bool diagHere = (rt == cq * 8 + i);
    #pragma unroll
    for (int mt = 0; mt < 2; mt++) {
        const unsigned w0 = cmask[labr[mt][0] * 32 + lw];
        const unsigned w1 = cmask[labr[mt][1] * 32 + lw];
        const int g0 = growb[mt], g1 = growb[mt] + 8;
        float t0 = 0.f, t1 = 0.f, p0 = 0.f, p1 = 0.f;
        #pragma unroll
        for (int ntl = 0; ntl < 4; ntl++) {
            const int sh = ntl * 8 + 2 * (lane & 3);
            const unsigned b0 = w0 >> sh;
            const unsigned b1 = w1 >> sh;
            float e00 = ex2f(acc[mt][ntl][0]);
            float e01 = ex2f(acc[mt][ntl][1]);
            float e10 = ex2f(acc[mt][ntl][2]);
            float e11 = ex2f(acc[mt][ntl][3]);
            if (diagHere) {
                const int gc = cb + ntl * 8 + 2 * (lane & 3);
                if (g0 == gc)     e00 = 0.f;
                if (g0 == gc + 1) e01 = 0.f;
                if (g1 == gc)     e10 = 0.f;
                if (g1 == gc + 1) e11 = 0.f;
            }
            t0 += e00 + e01;
            t1 += e10 + e11;
            p0 += ((b0 & 1u) ? e00 : 0.f) + ((b0 & 2u) ? e01 : 0.f);
            p1 += ((b1 & 1u) ? e10 : 0.f) + ((b1 & 2u) ? e11 : 0.f);
        }
        tot[mt * 2 + 0] += t0;  tot[mt * 2 + 1] += t1;
        pos[mt * 2 + 0] += p0;  pos[mt * 2 + 1] += p1;
    }
}

// ---------------------------------------------------------------------------
// Kernel 2: persistent HMMA GEMM + pipelined exp2/mask epilogue.
// Unit u: b = u>>7, rt = (u>>2)&31, cq = u&3. 128 rows x 1024 cols per unit.
// Dyn smem: A 32K | B0 32K | B1 32K | cmask 2K | posS 1K | totS 1K
// ---------------------------------------------------------------------------
#define SM_B0    32768
#define SM_B1    65536
#define SM_CMASK 98304
#define SM_POSS  (SM_CMASK + 2048)
#define SM_TOTS  (SM_POSS + 1024)
#define SM_DYN   (SM_TOTS + 1024)

__global__ void __launch_bounds__(256, 1)
loss_kernel(const int* __restrict__ labels) {
    extern __shared__ char sm[];
    const int tid = threadIdx.x, wid = tid >> 5, lane = tid & 31;

    unsigned* cmask = (unsigned*)(sm + SM_CMASK);   // [16 classes][32 words]
    float* posS = (float*)(sm + SM_POSS);           // [128][2]
    float* totS = (float*)(sm + SM_TOTS);

    const uint32_t sA  = smem_u32(sm);
    const uint32_t sB0 = smem_u32(sm + SM_B0);
    const uint32_t sB1 = smem_u32(sm + SM_B1);

    const int warpM = (wid & 3) * 32;
    const int warpN = (wid >> 2) * 64;

    // ldmatrix per-lane address components
    const int rA  = warpM + (lane & 15);
    const int csA = lane >> 4;
    const int rBl = (lane & 7) + ((lane & 16) >> 1);
    const int csB = (lane >> 3) & 1;

    uint32_t bRow[4];
    int bR7[4];
    #pragma unroll
    for (int np = 0; np < 4; np++) {
        int row = warpN + np * 16 + rBl;
        bRow[np] = (uint32_t)row * 256u;
        bR7[np] = row & 7;
    }

    int u = blockIdx.x;
    if (u < NU) {   // prologue loads for first unit
        const int b = u >> 7, rt = (u >> 2) & 31, cq = u & 3;
        const __half* vb = g_vh + (size_t)b * N_ * C_;
        cp_tile(sA,  vb + (size_t)(rt * TM) * C_, tid);
        cp_tile(sB0, vb + (size_t)(cq * 1024) * C_, tid);
        CP_COMMIT();
    }

    while (u < NU) {
        const int b = u >> 7, rt = (u >> 2) & 31, cq = u & 3;
        const int un = u + gridDim.x;
        const int* lb = labels + b * N_;
        const __half* vb = g_vh + (size_t)b * N_ * C_;

        CP_WAIT0();
        __syncthreads();    // A + B0 ready; prev unit fully done

        // per-class column bitmasks for this quarter (32 words per class)
        {
            int labv[4];
            #pragma unroll
            for (int i = 0; i < 4; i++)
                labv[i] = lb[cq * 1024 + (wid * 4 + i) * 32 + lane];
            #pragma unroll
            for (int i = 0; i < 4; i++)
                #pragma unroll
                for (int c = 0; c < 16; c++) {
                    unsigned m = __ballot_sync(0xffffffffu, labv[i] == c);
                    if (lane == c) cmask[c * 32 + wid * 4 + i] = m;
                }
        }

        // this thread's accumulator-row identities (in-batch rows)
        int growb[2], labr[2][2];
        #pragma unroll
        for (int mt = 0; mt < 2; mt++) {
            growb[mt] = rt * TM + warpM + mt * 16 + (lane >> 2);
            labr[mt][0] = lb[growb[mt]];
            labr[mt][1] = lb[growb[mt] + 8];
        }

        // A fragments cached in registers for the whole unit
        uint32_t af[2][8][4];
        #pragma unroll
        for (int mt = 0; mt < 2; mt++) {
            int row = rA + mt * 16;
            uint32_t base = sA + (uint32_t)row * 256u;
            int r7 = row & 7;
            #pragma unroll
            for (int k = 0; k < 8; k++) {
                uint32_t addr = base + (uint32_t)(((2 * k + csA) ^ r7) << 4);
                LDSM4(af[mt][k][0], af[mt][k][1], af[mt][k][2], af[mt][k][3],
                      addr);
            }
        }
        __syncthreads();    // cmask visible everywhere

        float pos[4] = {0.f, 0.f, 0.f, 0.f};
        float tot[4] = {0.f, 0.f, 0.f, 0.f};
        float acc0[2][4][4], acc1[2][4][4];

        for (int i = 0; i < IPU; i++) {
            const uint32_t sB = (i & 1) ? sB1 : sB0;
            // prefetch next tile (or next unit's A+B0 on the last iter)
            if (i < IPU - 1) {
                cp_tile(((i + 1) & 1) ? sB1 : sB0,
                        vb + (size_t)(cq * 1024 + (i + 1) * TN) * C_, tid);
                CP_COMMIT();
            } else if (un < NU) {
                const int bn = un >> 7, rtn = (un >> 2) & 31, cqn = un & 3;
                const __half* vbn = g_vh + (size_t)bn * N_ * C_;
                cp_tile(sA,  vbn + (size_t)(rtn * TM) * C_, tid);
                cp_tile(sB0, vbn + (size_t)(cqn * 1024) * C_, tid);
                CP_COMMIT();
            }

            // pipelined: K0(i), E1(i-1), K1(i), E0(i)
            khalf(acc0, af, sB, bRow[0], bR7[0], bRow[1], bR7[1], csB);
            if (i > 0)
                epi_half(acc1, i - 1, 1, cmask, labr, growb, warpN, lane,
                         rt, cq, pos, tot);
            khalf(acc1, af, sB, bRow[2], bR7[2], bRow[3], bR7[3], csB);
            epi_half(acc0, i, 0, cmask, labr, growb, warpN, lane,
                     rt, cq, pos, tot);

            CP_WAIT0();
            __syncthreads();
        }
        // flush pending last half
        epi_half(acc1, IPU - 1, 1, cmask, labr, growb, warpN, lane,
                 rt, cq, pos, tot);

        // reduce 4 lanes sharing each row, merge 2 N-warps, atomic to global
        #pragma unroll
        for (int q = 0; q < 4; q++) {
            pos[q] += __shfl_xor_sync(0xffffffffu, pos[q], 1);
            pos[q] += __shfl_xor_sync(0xffffffffu, pos[q], 2);
            tot[q] += __shfl_xor_sync(0xffffffffu, tot[q], 1);
            tot[q] += __shfl_xor_sync(0xffffffffu, tot[q], 2);
        }
        const int widN = wid >> 2;
        if ((lane & 3) == 0) {
            #pragma unroll
            for (int mt = 0; mt < 2; mt++) {
                int rl = warpM + mt * 16 + (lane >> 2);
                posS[rl * 2 + widN]       = pos[mt * 2 + 0];
                totS[rl * 2 + widN]       = tot[mt * 2 + 0];
                posS[(rl + 8) * 2 + widN] = pos[mt * 2 + 1];
                totS[(rl + 8) * 2 + widN] = tot[mt * 2 + 1];
            }
        }
        __syncthreads();
        if (tid < TM) {
            float P = posS[tid * 2] + posS[tid * 2 + 1];
            float T = totS[tid * 2] + totS[tid * 2 + 1];
            int gr = b * N_ + rt * TM + tid;
            atomicAdd(&g_pos[gr], P);
            atomicAdd(&g_tot[gr], T);
        }
        u = un;
    }
}

// ---------------------------------------------------------------------------
// Kernel 3: finalize — dev = log(T) - log(P) per row, mean into out.
// ---------------------------------------------------------------------------
__global__ void finalize_kernel(float* __restrict__ out) {
    __shared__ float ws[8];
    const int idx = blockIdx.x * 256 + threadIdx.x;
    const int lane = threadIdx.x & 31, wid = threadIdx.x >> 5;
    float dev = __logf(g_tot[idx]) - __logf(g_pos[idx]);
    #pragma unroll
    for (int o = 16; o > 0; o >>= 1) dev += __shfl_xor_sync(0xffffffffu, dev, o);
    if (lane == 0) ws[wid] = dev;
    __syncthreads();
    if (threadIdx.x == 0) {
        float s = 0.0f;
        #pragma unroll
        for (int w = 0; w < 8; w++) s += ws[w];
        atomicAdd(out, s * (1.0f / ((float)B_ * (float)N_)));
    }
}

// ---------------------------------------------------------------------------
// Launch
// ---------------------------------------------------------------------------
extern "C" void kernel_launch(void* const* d_in, const int* in_sizes, int n_in,
                              void* d_out, int out_size) {
    const float* feat   = (const float*)d_in[0];
    const int*   labels = (const int*)d_in[1];
    float*       out    = (float*)d_out;

    zero_kernel<<<128, 256>>>(out);

    dim3 gn(N_ / 32, B_);
    normalize_kernel<<<gn, 256>>>(feat);

    cudaFuncSetAttribute(loss_kernel,
                         cudaFuncAttributeMaxDynamicSharedMemorySize, SM_DYN);
    loss_kernel<<<GRIDP, 256, SM_DYN>>>(labels);

    finalize_kernel<<<(B_ * N_) / 256, 256>>>(out);
}